// round 1
// baseline (speedup 1.0000x reference)
#include <cuda_runtime.h>

#define N_NODES 100000
#define N_EDGES 1600000
#define DF      128
#define TS      68   // padded smem row stride (floats)

// ---------------- scratch (device globals: allocation-free) ----------------
static __device__ float g_k[(size_t)N_NODES * DF];
static __device__ float g_q[(size_t)N_NODES * DF];
static __device__ float g_v[(size_t)N_NODES * DF];
static __device__ float g_s[(size_t)N_NODES * DF];
static __device__ float g_h0[(size_t)N_NODES * DF];
static __device__ float g_h1[(size_t)N_NODES * DF];
static __device__ int   g_rowptr[N_NODES + 1];
static __device__ int   g_fill[N_NODES];
static __device__ int   g_esrc[N_EDGES];

// ---------------- CSR build ----------------
__global__ void zero_cnt_kernel() {
    int i = blockIdx.x * blockDim.x + threadIdx.x;
    if (i < N_NODES) g_fill[i] = 0;
}

__global__ void hist_kernel(const int* __restrict__ dst) {
    int e = blockIdx.x * blockDim.x + threadIdx.x;
    if (e < N_EDGES) atomicAdd(&g_fill[dst[e]], 1);
}

// single-block exclusive scan of g_fill -> g_rowptr (and reset g_fill = rowptr)
__global__ void scan_kernel() {
    __shared__ int wsum[32];
    __shared__ int carry;
    int tid = threadIdx.x, lane = tid & 31, wid = tid >> 5;
    if (tid == 0) carry = 0;
    __syncthreads();
    for (int base = 0; base < N_NODES; base += 1024) {
        int idx = base + tid;
        int v = (idx < N_NODES) ? g_fill[idx] : 0;
        int x = v;
#pragma unroll
        for (int o = 1; o < 32; o <<= 1) {
            int t = __shfl_up_sync(0xffffffffu, x, o);
            if (lane >= o) x += t;
        }
        if (lane == 31) wsum[wid] = x;
        __syncthreads();
        if (wid == 0) {
            int y = wsum[lane];
#pragma unroll
            for (int o = 1; o < 32; o <<= 1) {
                int t = __shfl_up_sync(0xffffffffu, y, o);
                if (lane >= o) y += t;
            }
            wsum[lane] = y;
        }
        __syncthreads();
        int excl = carry + (x - v) + (wid ? wsum[wid - 1] : 0);
        if (idx < N_NODES) { g_rowptr[idx] = excl; g_fill[idx] = excl; }
        __syncthreads();
        if (tid == 0) carry += wsum[31];
        __syncthreads();
    }
    if (tid == 0) g_rowptr[N_NODES] = N_EDGES;
}

__global__ void scatter_kernel(const int* __restrict__ src, const int* __restrict__ dst) {
    int e = blockIdx.x * blockDim.x + threadIdx.x;
    if (e < N_EDGES) {
        int d = dst[e];
        int p = atomicAdd(&g_fill[d], 1);
        g_esrc[p] = src[e];
    }
}

// ---------------- fused 4-way GEMM: {k,q,v,s} = X @ {Wk,Wq,Wv,Ws} (+bias on s) ----
// grid = (8 column-tiles, 1563 row-tiles), 256 threads, 64x64 tile, K=128 resident.
__global__ void __launch_bounds__(256) gemm4_kernel(
    const float* __restrict__ Xext, int xsel,
    const float* __restrict__ Wk, const float* __restrict__ Wq,
    const float* __restrict__ Wv, const float* __restrict__ Ws,
    const float* __restrict__ bias)
{
    extern __shared__ float sm[];
    float* As = sm;             // [128][TS] transposed X tile: As[k][m]
    float* Bs = sm + 128 * TS;  // [128][TS] W tile:            Bs[k][n]

    const float* X = xsel ? g_h0 : Xext;

    int tid = threadIdx.x;
    int tx = tid & 15, ty = tid >> 4;
    int c = blockIdx.x;                 // 0..7 column tile
    int row0 = blockIdx.y * 64;
    int mat = c >> 1;
    int off = (c & 1) * 64;
    const float* W  = (mat == 0) ? Wk : (mat == 1) ? Wq : (mat == 2) ? Wv : Ws;
    float*       Out = (mat == 0) ? g_k : (mat == 1) ? g_q : (mat == 2) ? g_v : g_s;

    // load X tile (64 rows x 128 cols) transposed into As
#pragma unroll
    for (int p = 0; p < 8; p++) {
        int f = tid + p * 256;          // 0..2047
        int r  = f >> 5;                // 0..63
        int kq = (f & 31) << 2;         // 0..124
        int gr = row0 + r;
        float4 xv = make_float4(0.f, 0.f, 0.f, 0.f);
        if (gr < N_NODES)
            xv = *reinterpret_cast<const float4*>(X + (size_t)gr * DF + kq);
        As[(kq + 0) * TS + r] = xv.x;
        As[(kq + 1) * TS + r] = xv.y;
        As[(kq + 2) * TS + r] = xv.z;
        As[(kq + 3) * TS + r] = xv.w;
    }
    // load W tile (128 rows x 64 cols)
#pragma unroll
    for (int p = 0; p < 8; p++) {
        int f = tid + p * 256;
        int kk = f >> 4;                // 0..127
        int nq = (f & 15) << 2;         // 0..60
        float4 wv = *reinterpret_cast<const float4*>(W + (size_t)kk * DF + off + nq);
        *reinterpret_cast<float4*>(&Bs[kk * TS + nq]) = wv;
    }
    __syncthreads();

    unsigned long long acc[4][2];
#pragma unroll
    for (int i = 0; i < 4; i++) { acc[i][0] = 0ull; acc[i][1] = 0ull; }

    int ty4 = ty * 4, tx4 = tx * 4;
#pragma unroll 8
    for (int k = 0; k < 128; k++) {
        float4 a = *reinterpret_cast<const float4*>(&As[k * TS + ty4]);
        float4 b = *reinterpret_cast<const float4*>(&Bs[k * TS + tx4]);
        unsigned long long b01, b23;
        asm("mov.b64 %0,{%1,%2};" : "=l"(b01)
            : "r"(__float_as_uint(b.x)), "r"(__float_as_uint(b.y)));
        asm("mov.b64 %0,{%1,%2};" : "=l"(b23)
            : "r"(__float_as_uint(b.z)), "r"(__float_as_uint(b.w)));
        float av[4] = {a.x, a.y, a.z, a.w};
#pragma unroll
        for (int i = 0; i < 4; i++) {
            unsigned long long aii;
            asm("mov.b64 %0,{%1,%1};" : "=l"(aii) : "r"(__float_as_uint(av[i])));
            asm("fma.rn.f32x2 %0,%1,%2,%0;" : "+l"(acc[i][0]) : "l"(aii), "l"(b01));
            asm("fma.rn.f32x2 %0,%1,%2,%0;" : "+l"(acc[i][1]) : "l"(aii), "l"(b23));
        }
    }

    float4 bb = make_float4(0.f, 0.f, 0.f, 0.f);
    if (mat == 3) bb = *reinterpret_cast<const float4*>(bias + off + tx4);
#pragma unroll
    for (int i = 0; i < 4; i++) {
        int gr = row0 + ty4 + i;
        if (gr < N_NODES) {
            float2 p0 = *reinterpret_cast<float2*>(&acc[i][0]);
            float2 p1 = *reinterpret_cast<float2*>(&acc[i][1]);
            float4 r = make_float4(p0.x + bb.x, p0.y + bb.y, p1.x + bb.z, p1.y + bb.w);
            *reinterpret_cast<float4*>(Out + (size_t)gr * DF + off + tx4) = r;
        }
    }
}

// ---------------- edge aggregation: one warp per destination node ----------------
__global__ void agg_kernel(int osel, int do_relu) {
    int gw = (blockIdx.x * blockDim.x + threadIdx.x) >> 5;
    if (gw >= N_NODES) return;
    int lane = threadIdx.x & 31;
    float* out = osel ? g_h1 : g_h0;

    size_t fo = (size_t)gw * DF + lane * 4;
    float4 kk = *reinterpret_cast<const float4*>(g_k + fo);
    float4 acc = make_float4(0.f, 0.f, 0.f, 0.f);

    int beg = g_rowptr[gw], end = g_rowptr[gw + 1];
    for (int j = beg; j < end; j++) {
        int s = g_esrc[j];
        size_t so = (size_t)s * DF + lane * 4;
        float4 qq = *reinterpret_cast<const float4*>(g_q + so);
        float4 vv = *reinterpret_cast<const float4*>(g_v + so);
        acc.x += __fdividef(vv.x, 1.f + __expf(-(kk.x + qq.x)));
        acc.y += __fdividef(vv.y, 1.f + __expf(-(kk.y + qq.y)));
        acc.z += __fdividef(vv.z, 1.f + __expf(-(kk.z + qq.z)));
        acc.w += __fdividef(vv.w, 1.f + __expf(-(kk.w + qq.w)));
    }
    float4 ss = *reinterpret_cast<const float4*>(g_s + fo);
    float4 r = make_float4(acc.x + ss.x, acc.y + ss.y, acc.z + ss.z, acc.w + ss.w);
    if (do_relu) {
        r.x = fmaxf(r.x, 0.f); r.y = fmaxf(r.y, 0.f);
        r.z = fmaxf(r.z, 0.f); r.w = fmaxf(r.w, 0.f);
    }
    *reinterpret_cast<float4*>(out + fo) = r;
}

// ---------------- layer 3 (D_OUT = 1) ----------------
__global__ void gemm3_kernel(const float* __restrict__ Wk, const float* __restrict__ Wq,
                             const float* __restrict__ Wv, const float* __restrict__ Ws,
                             const float* __restrict__ bias)
{
    int gw = (blockIdx.x * blockDim.x + threadIdx.x) >> 5;
    if (gw >= N_NODES) return;
    int lane = threadIdx.x & 31;
    float4 x4 = *reinterpret_cast<const float4*>(g_h1 + (size_t)gw * DF + lane * 4);
    float4 wk = *reinterpret_cast<const float4*>(Wk + lane * 4);
    float4 wq = *reinterpret_cast<const float4*>(Wq + lane * 4);
    float4 wv = *reinterpret_cast<const float4*>(Wv + lane * 4);
    float4 ws = *reinterpret_cast<const float4*>(Ws + lane * 4);
    float pk = x4.x * wk.x + x4.y * wk.y + x4.z * wk.z + x4.w * wk.w;
    float pq = x4.x * wq.x + x4.y * wq.y + x4.z * wq.z + x4.w * wq.w;
    float pv = x4.x * wv.x + x4.y * wv.y + x4.z * wv.z + x4.w * wv.w;
    float ps = x4.x * ws.x + x4.y * ws.y + x4.z * ws.z + x4.w * ws.w;
#pragma unroll
    for (int o = 16; o; o >>= 1) {
        pk += __shfl_xor_sync(0xffffffffu, pk, o);
        pq += __shfl_xor_sync(0xffffffffu, pq, o);
        pv += __shfl_xor_sync(0xffffffffu, pv, o);
        ps += __shfl_xor_sync(0xffffffffu, ps, o);
    }
    if (lane == 0) {
        g_k[gw] = pk; g_q[gw] = pq; g_v[gw] = pv; g_s[gw] = ps + bias[0];
    }
}

__global__ void agg3_kernel(float* __restrict__ out) {
    int i = blockIdx.x * blockDim.x + threadIdx.x;
    if (i >= N_NODES) return;
    float ki = g_k[i];
    float acc = 0.f;
    int end = g_rowptr[i + 1];
    for (int j = g_rowptr[i]; j < end; j++) {
        int s = g_esrc[j];
        acc += __fdividef(g_v[s], 1.f + __expf(-(ki + g_q[s])));
    }
    out[i] = acc + g_s[i];
}

// ---------------- launch ----------------
extern "C" void kernel_launch(void* const* d_in, const int* in_sizes, int n_in,
                              void* d_out, int out_size) {
    const float* x   = (const float*)d_in[0];
    const int*   ei  = (const int*)d_in[1];
    const int*   src = ei;
    const int*   dst = ei + N_EDGES;
    const float* Wk1 = (const float*)d_in[2];
    const float* Wq1 = (const float*)d_in[3];
    const float* Wv1 = (const float*)d_in[4];
    const float* Ws1 = (const float*)d_in[5];
    const float* b1  = (const float*)d_in[6];
    const float* Wk2 = (const float*)d_in[7];
    const float* Wq2 = (const float*)d_in[8];
    const float* Wv2 = (const float*)d_in[9];
    const float* Ws2 = (const float*)d_in[10];
    const float* b2  = (const float*)d_in[11];
    const float* Wk3 = (const float*)d_in[12];
    const float* Wq3 = (const float*)d_in[13];
    const float* Wv3 = (const float*)d_in[14];
    const float* Ws3 = (const float*)d_in[15];
    const float* b3  = (const float*)d_in[16];
    float* out = (float*)d_out;

    const int smem = 2 * 128 * TS * sizeof(float);  // 69632
    cudaFuncSetAttribute(gemm4_kernel, cudaFuncAttributeMaxDynamicSharedMemorySize, smem);

    // CSR build (reused by all 3 layers)
    zero_cnt_kernel<<<(N_NODES + 255) / 256, 256>>>();
    hist_kernel<<<(N_EDGES + 255) / 256, 256>>>(dst);
    scan_kernel<<<1, 1024>>>();
    scatter_kernel<<<(N_EDGES + 255) / 256, 256>>>(src, dst);

    dim3 ggrid(8, (N_NODES + 63) / 64);
    int  agg_blocks = (N_NODES * 32 + 255) / 256;

    // layer 1
    gemm4_kernel<<<ggrid, 256, smem>>>(x, 0, Wk1, Wq1, Wv1, Ws1, b1);
    agg_kernel<<<agg_blocks, 256>>>(0, 1);
    // layer 2
    gemm4_kernel<<<ggrid, 256, smem>>>(nullptr, 1, Wk2, Wq2, Wv2, Ws2, b2);
    agg_kernel<<<agg_blocks, 256>>>(1, 1);
    // layer 3
    gemm3_kernel<<<agg_blocks, 256>>>(Wk3, Wq3, Wv3, Ws3, b3);
    agg3_kernel<<<(N_NODES + 255) / 256, 256>>>(out);
}